// round 14
// baseline (speedup 1.0000x reference)
#include <cuda_runtime.h>
#include <cuda_bf16.h>
#include <cstdint>

#define N_NODES 50000
#define N_EDGES 800000
#define FD      128
#define NF4     (N_NODES * (FD/4))

// ---- scratch (static __device__ arrays: allocation-free, zero-initialized) ----
__device__ __align__(16) float g_node [N_NODES * FD];
__device__ __align__(16) float g_emean[N_NODES * FD];
__device__ __align__(16) float g_h    [N_NODES * FD];
__device__ __align__(16) float g_tmp  [N_NODES * FD];
__device__ __align__(16) __nv_bfloat16 g_wh[4 * 256 * 128];
__device__ __align__(16) __nv_bfloat16 g_wl[4 * 256 * 128];
__device__ float g_p1[N_NODES];    // node . Wf[0:128]
__device__ int g_cnt_d[N_NODES];
__device__ int g_cnt_s[N_NODES];
__device__ int g_len_d[N_NODES];
__device__ int g_len_s[N_NODES];
__device__ int g_off_d[N_NODES];
__device__ int g_off_s[N_NODES];
__device__ int g_cur_d[N_NODES];
__device__ int g_cur_s[N_NODES];
__device__ int g_lst_d[N_EDGES];
__device__ int g_src_d[N_EDGES];
__device__ int g_lst_s[N_EDGES];
__device__ int g_tot_d;
__device__ int g_tot_s;
__device__ int g_mode;

// ======================= helpers =======================
__device__ __forceinline__ uint32_t smem_u32(const void* p) {
    uint32_t a;
    asm("{ .reg .u64 t; cvta.to.shared.u64 t, %1; cvt.u32.u64 %0, t; }"
        : "=r"(a) : "l"(p));
    return a;
}

__device__ __forceinline__ void ldm_x4(uint32_t& r0, uint32_t& r1, uint32_t& r2,
                                       uint32_t& r3, uint32_t addr) {
    asm volatile("ldmatrix.sync.aligned.m8n8.x4.shared.b16 {%0,%1,%2,%3}, [%4];"
                 : "=r"(r0), "=r"(r1), "=r"(r2), "=r"(r3) : "r"(addr));
}

__device__ __forceinline__ void mma16816(float& d0, float& d1, float& d2, float& d3,
                                         uint32_t a0, uint32_t a1, uint32_t a2, uint32_t a3,
                                         uint32_t b0, uint32_t b1) {
    asm volatile("mma.sync.aligned.m16n8k16.row.col.f32.bf16.bf16.f32 "
                 "{%0,%1,%2,%3}, {%4,%5,%6,%7}, {%8,%9}, {%0,%1,%2,%3};"
                 : "+f"(d0), "+f"(d1), "+f"(d2), "+f"(d3)
                 : "r"(a0), "r"(a1), "r"(a2), "r"(a3), "r"(b0), "r"(b1));
}

// ======================= fused W prep (4 slots) + dtype detect =======================
__global__ void k_prep(const float* __restrict__ W0e, const float* __restrict__ W0n,
                       const float* __restrict__ W1e, const float* __restrict__ W1n,
                       const int* __restrict__ idx32) {
    int slot = blockIdx.x >> 7;
    const float* W = (slot == 0) ? W0e : (slot == 1) ? W0n : (slot == 2) ? W1e : W1n;
    int idx = (blockIdx.x & 127) * 256 + threadIdx.x;
    int n = idx >> 8, k = idx & 255;
    float x = W[k * 128 + n];
    __nv_bfloat16 hi = __float2bfloat16_rn(x);
    __nv_bfloat16 lo = __float2bfloat16_rn(x - __bfloat162float(hi));
    g_wh[slot * 32768 + n * 256 + k] = hi;
    g_wl[slot * 32768 + n * 256 + k] = lo;
    if (blockIdx.x == 0 && threadIdx.x == 0) {
        int nz = 0;
        for (int j = 0; j < 512; j++) nz += (idx32[2 * j + 1] != 0);
        g_mode = (nz == 0) ? 1 : 0;
    }
}

__device__ __forceinline__ int clampn(int v) { return min(max(v, 0), N_NODES - 1); }

__device__ __forceinline__ void load_sd2(const void* __restrict__ idx, int e2,
                                         int& s0, int& d0, int& s1, int& d1) {
    if (g_mode) {
        const longlong2* p = (const longlong2*)idx;
        longlong2 sp = p[e2];
        longlong2 dp = p[e2 + N_EDGES / 2];
        s0 = clampn((int)sp.x); s1 = clampn((int)sp.y);
        d0 = clampn((int)dp.x); d1 = clampn((int)dp.y);
    } else {
        const int2* p = (const int2*)idx;
        int2 sp = p[e2];
        int2 dp = p[e2 + N_EDGES / 2];
        s0 = clampn(sp.x); s1 = clampn(sp.y);
        d0 = clampn(dp.x); d1 = clampn(dp.y);
    }
}

__global__ void k_hist(const void* __restrict__ idx) {
    int t = blockIdx.x * blockDim.x + threadIdx.x;
    if (t >= N_EDGES / 2) return;
    int s0, d0, s1, d1;
    load_sd2(idx, t, s0, d0, s1, d1);
    atomicAdd(&g_cnt_d[d0], 1);
    atomicAdd(&g_cnt_d[d1], 1);
    atomicAdd(&g_cnt_s[s0], 1);
    atomicAdd(&g_cnt_s[s1], 1);
}

__global__ void k_alloc() {
    int i = blockIdx.x * blockDim.x + threadIdx.x;
    if (i >= N_NODES) return;
    int cd = g_cnt_d[i];
    g_cnt_d[i] = 0;
    g_len_d[i] = cd;
    int od = atomicAdd(&g_tot_d, cd);
    g_off_d[i] = od;
    g_cur_d[i] = od;
    int cs = g_cnt_s[i];
    g_cnt_s[i] = 0;
    g_len_s[i] = cs;
    int os = atomicAdd(&g_tot_s, cs);
    g_off_s[i] = os;
    g_cur_s[i] = os;
}

__global__ void k_fill(const void* __restrict__ idx) {
    int t = blockIdx.x * blockDim.x + threadIdx.x;
    if (t == 0) { g_tot_d = 0; g_tot_s = 0; }
    if (t >= N_EDGES / 2) return;
    int s0, d0, s1, d1;
    load_sd2(idx, t, s0, d0, s1, d1);
    int e0 = 2 * t, e1 = 2 * t + 1;
    int pd0 = min(max(atomicAdd(&g_cur_d[d0], 1), 0), N_EDGES - 1);
    g_lst_d[pd0] = e0; g_src_d[pd0] = s0;
    int pd1 = min(max(atomicAdd(&g_cur_d[d1], 1), 0), N_EDGES - 1);
    g_lst_d[pd1] = e1; g_src_d[pd1] = s1;
    int ps0 = min(max(atomicAdd(&g_cur_s[s0], 1), 0), N_EDGES - 1);
    g_lst_s[ps0] = e0;
    int ps1 = min(max(atomicAdd(&g_cur_s[s1], 1), 0), N_EDGES - 1);
    g_lst_s[ps1] = e1;
}

// ---- 8-deep unrolled mean gather over a CSR segment (warp per node) ----
__device__ __forceinline__ float4 seg_mean_rows(const float4* __restrict__ base,
                                                const int* __restrict__ lst,
                                                int b, int n, int lane, int clampmax) {
    int e = min(b + n, N_EDGES);
    float4 acc = make_float4(0.f, 0.f, 0.f, 0.f);
    int i = b;
    for (; i + 8 <= e; i += 8) {
        int ix[8];
        #pragma unroll
        for (int u = 0; u < 8; u++) ix[u] = min(max(lst[i + u], 0), clampmax);
        float4 v[8];
        #pragma unroll
        for (int u = 0; u < 8; u++) v[u] = base[(size_t)ix[u] * 32 + lane];
        #pragma unroll
        for (int u = 0; u < 8; u++) {
            acc.x += v[u].x; acc.y += v[u].y; acc.z += v[u].z; acc.w += v[u].w;
        }
    }
    for (; i < e; i++) {
        int i0 = min(max(lst[i], 0), clampmax);
        float4 v = base[(size_t)i0 * 32 + lane];
        acc.x += v.x; acc.y += v.y; acc.z += v.z; acc.w += v.w;
    }
    float inv = 1.0f / fmaxf((float)n, 1.0f);
    acc.x *= inv; acc.y *= inv; acc.z *= inv; acc.w *= inv;
    return acc;
}

// two warps per node: even warp does dst-mean -> g_node, odd warp src-mean -> g_emean
__global__ void k_gather_means(const float* __restrict__ ea) {
    int gid = blockIdx.x * blockDim.x + threadIdx.x;
    int wg = gid >> 5, lane = gid & 31;
    int w = wg >> 1;
    if (w >= N_NODES) return;
    const float4* ea4 = (const float4*)ea;
    if ((wg & 1) == 0) {
        ((float4*)g_node)[(size_t)w * 32 + lane] =
            seg_mean_rows(ea4, g_lst_d, g_off_d[w], g_len_d[w], lane, N_EDGES - 1);
    } else {
        ((float4*)g_emean)[(size_t)w * 32 + lane] =
            seg_mean_rows(ea4, g_lst_s, g_off_s[w], g_len_s[w], lane, N_EDGES - 1);
    }
}

__global__ void k_gather_neigh() {
    int gid = blockIdx.x * blockDim.x + threadIdx.x;
    int w = gid >> 5, lane = gid & 31;
    if (w >= N_NODES) return;
    ((float4*)g_tmp)[(size_t)w * 32 + lane] =
        seg_mean_rows((const float4*)g_h, g_src_d, g_off_d[w], g_len_d[w], lane,
                      N_NODES - 1);
}

// ======================= bf16 split-precision HMMA GEMM (double-buffered) =======================
#define SROW   40
#define BUFB   10240
#define BUFSTR (4 * BUFB)
#define SMTOT  (2 * BUFSTR)

__global__ void __launch_bounds__(256, 2) k_gemm_mma(
        int slot, const float* __restrict__ bias, int sel, float* __restrict__ out2) {
    extern __shared__ __align__(16) char dsm[];
    const float* A;
    const float* Bm;
    float* out;
    if (sel == 0) { A = g_node; Bm = g_emean; out = g_h; }
    else          { A = g_h;    Bm = g_tmp;   out = g_node; }
    const __nv_bfloat16* Wh = g_wh + (size_t)slot * 32768;
    const __nv_bfloat16* Wl = g_wl + (size_t)slot * 32768;

    int tid  = threadIdx.x;
    int lane = tid & 31;
    int wid  = tid >> 5;
    int m0   = blockIdx.x * 128;
    int warp_m = wid >> 2;
    int warp_n = wid & 3;

    int l7 = lane & 7;
    int a_ro = l7 + ((lane >> 3) & 1) * 8;
    int a_ko = (lane >> 4) * 8;
    int b_no = l7 + (lane >> 4) * 8;
    int b_ko = ((lane >> 3) & 1) * 8;

    float acc[4][4][4];
    #pragma unroll
    for (int i = 0; i < 4; i++)
        #pragma unroll
        for (int j = 0; j < 4; j++)
            #pragma unroll
            for (int r = 0; r < 4; r++) acc[i][j][r] = 0.f;

    {
        __nv_bfloat16* Ah = (__nv_bfloat16*)(dsm);
        __nv_bfloat16* Al = (__nv_bfloat16*)(dsm + BUFB);
        __nv_bfloat16* Bh = (__nv_bfloat16*)(dsm + 2 * BUFB);
        __nv_bfloat16* Bl = (__nv_bfloat16*)(dsm + 3 * BUFB);
        #pragma unroll
        for (int it = 0; it < 4; it++) {
            int f = tid + it * 256;
            int row = f >> 3, q = f & 7;
            int grow = m0 + row;
            float4 v = make_float4(0.f, 0.f, 0.f, 0.f);
            if (grow < N_NODES) v = *(const float4*)(A + (size_t)grow * FD + q * 4);
            __nv_bfloat162 h0 = __float22bfloat162_rn(make_float2(v.x, v.y));
            __nv_bfloat162 h1 = __float22bfloat162_rn(make_float2(v.z, v.w));
            float2 f0 = __bfloat1622float2(h0);
            float2 f1 = __bfloat1622float2(h1);
            __nv_bfloat162 l0 = __float22bfloat162_rn(make_float2(v.x - f0.x, v.y - f0.y));
            __nv_bfloat162 l1 = __float22bfloat162_rn(make_float2(v.z - f1.x, v.w - f1.y));
            uint2 uh, ul;
            uh.x = *(uint32_t*)&h0; uh.y = *(uint32_t*)&h1;
            ul.x = *(uint32_t*)&l0; ul.y = *(uint32_t*)&l1;
            *(uint2*)&Ah[row * SROW + q * 4] = uh;
            *(uint2*)&Al[row * SROW + q * 4] = ul;
            *(uint2*)&Bh[row * SROW + q * 4] = *(const uint2*)(Wh + row * 256 + q * 4);
            *(uint2*)&Bl[row * SROW + q * 4] = *(const uint2*)(Wl + row * 256 + q * 4);
        }
    }
    __syncthreads();

    #pragma unroll 1
    for (int ch = 0; ch < 8; ch++) {
        char* cur = dsm + (ch & 1) * BUFSTR;
        char* nxt = dsm + ((ch + 1) & 1) * BUFSTR;
        __nv_bfloat16* Ah = (__nv_bfloat16*)(cur);
        __nv_bfloat16* Al = (__nv_bfloat16*)(cur + BUFB);
        __nv_bfloat16* Bh = (__nv_bfloat16*)(cur + 2 * BUFB);
        __nv_bfloat16* Bl = (__nv_bfloat16*)(cur + 3 * BUFB);

        float4 av[4];
        if (ch < 7) {
            int kb2 = (ch + 1) * 32;
            const float* X2 = (kb2 < 128) ? A : Bm;
            int ko2 = kb2 & 127;
            #pragma unroll
            for (int it = 0; it < 4; it++) {
                int f = tid + it * 256;
                int row = f >> 3, q = f & 7;
                int grow = m0 + row;
                av[it] = make_float4(0.f, 0.f, 0.f, 0.f);
                if (grow < N_NODES)
                    av[it] = *(const float4*)(X2 + (size_t)grow * FD + ko2 + q * 4);
            }
            __nv_bfloat16* nBh = (__nv_bfloat16*)(nxt + 2 * BUFB);
            __nv_bfloat16* nBl = (__nv_bfloat16*)(nxt + 3 * BUFB);
            #pragma unroll
            for (int it = 0; it < 4; it++) {
                int f = tid + it * 256;
                int n = f >> 3, q = f & 7;
                *(uint2*)&nBh[n * SROW + q * 4] = *(const uint2*)(Wh + n * 256 + kb2 + q * 4);
                *(uint2*)&nBl[n * SROW + q * 4] = *(const uint2*)(Wl + n * 256 + kb2 + q * 4);
            }
        }

        #pragma unroll
        for (int ks = 0; ks < 2; ks++) {
            int kl = ks * 16;
            uint32_t bh[2][4], bl[2][4];
            #pragma unroll
            for (int jp = 0; jp < 2; jp++) {
                int nn = warp_n * 32 + jp * 16 + b_no;
                int kk = kl + b_ko;
                ldm_x4(bh[jp][0], bh[jp][1], bh[jp][2], bh[jp][3],
                       smem_u32(&Bh[nn * SROW + kk]));
                ldm_x4(bl[jp][0], bl[jp][1], bl[jp][2], bl[jp][3],
                       smem_u32(&Bl[nn * SROW + kk]));
            }
            #pragma unroll
            for (int i = 0; i < 4; i++) {
                int row = warp_m * 64 + i * 16 + a_ro;
                int kk  = kl + a_ko;
                uint32_t ah0, ah1, ah2, ah3, al0, al1, al2, al3;
                ldm_x4(ah0, ah1, ah2, ah3, smem_u32(&Ah[row * SROW + kk]));
                ldm_x4(al0, al1, al2, al3, smem_u32(&Al[row * SROW + kk]));
                #pragma unroll
                for (int j = 0; j < 4; j++) {
                    uint32_t b0h = bh[j >> 1][(j & 1) * 2], b1h = bh[j >> 1][(j & 1) * 2 + 1];
                    uint32_t b0l = bl[j >> 1][(j & 1) * 2], b1l = bl[j >> 1][(j & 1) * 2 + 1];
                    float* c = acc[i][j];
                    mma16816(c[0], c[1], c[2], c[3], ah0, ah1, ah2, ah3, b0h, b1h);
                    mma16816(c[0], c[1], c[2], c[3], ah0, ah1, ah2, ah3, b0l, b1l);
                    mma16816(c[0], c[1], c[2], c[3], al0, al1, al2, al3, b0h, b1h);
                }
            }
        }

        if (ch < 7) {
            __nv_bfloat16* nAh = (__nv_bfloat16*)(nxt);
            __nv_bfloat16* nAl = (__nv_bfloat16*)(nxt + BUFB);
            #pragma unroll
            for (int it = 0; it < 4; it++) {
                int f = tid + it * 256;
                int row = f >> 3, q = f & 7;
                float4 v = av[it];
                __nv_bfloat162 h0 = __float22bfloat162_rn(make_float2(v.x, v.y));
                __nv_bfloat162 h1 = __float22bfloat162_rn(make_float2(v.z, v.w));
                float2 f0 = __bfloat1622float2(h0);
                float2 f1 = __bfloat1622float2(h1);
                __nv_bfloat162 l0 = __float22bfloat162_rn(make_float2(v.x - f0.x, v.y - f0.y));
                __nv_bfloat162 l1 = __float22bfloat162_rn(make_float2(v.z - f1.x, v.w - f1.y));
                uint2 uh, ul;
                uh.x = *(uint32_t*)&h0; uh.y = *(uint32_t*)&h1;
                ul.x = *(uint32_t*)&l0; ul.y = *(uint32_t*)&l1;
                *(uint2*)&nAh[row * SROW + q * 4] = uh;
                *(uint2*)&nAl[row * SROW + q * 4] = ul;
            }
        }
        __syncthreads();
    }

    int gID = lane >> 2, tig = lane & 3;
    #pragma unroll
    for (int j = 0; j < 4; j++) {
        int col = warp_n * 32 + j * 8 + tig * 2;
        float bv0 = __ldg(bias + col);
        float bv1 = __ldg(bias + col + 1);
        #pragma unroll
        for (int i = 0; i < 4; i++) {
            int r0 = m0 + warp_m * 64 + i * 16 + gID;
            float* c = acc[i][j];
            if (r0 < N_NODES) {
                float2 o;
                o.x = fmaxf(c[0] + bv0, 0.f);
                o.y = fmaxf(c[1] + bv1, 0.f);
                *(float2*)(out + (size_t)r0 * FD + col) = o;
                if (out2) __stcs((float2*)(out2 + (size_t)r0 * FD + col), o);
            }
            int r1 = r0 + 8;
            if (r1 < N_NODES) {
                float2 o;
                o.x = fmaxf(c[2] + bv0, 0.f);
                o.y = fmaxf(c[3] + bv1, 0.f);
                *(float2*)(out + (size_t)r1 * FD + col) = o;
                if (out2) __stcs((float2*)(out2 + (size_t)r1 * FD + col), o);
            }
        }
    }
}

// ---- per-node logit partial: p1 = node . Wf[0:128] (L2-resident, ~10us) ----
__global__ void k_node_logit(const float* __restrict__ Wf) {
    int gid = blockIdx.x * blockDim.x + threadIdx.x;
    int w = gid >> 5, lane = gid & 31;
    if (w >= N_NODES) return;
    float4 nv = ((const float4*)g_node)[(size_t)w * 32 + lane];
    float4 w0 = __ldg((const float4*)Wf + lane);
    float p1 = nv.x*w0.x + nv.y*w0.y + nv.z*w0.z + nv.w*w0.w;
    #pragma unroll
    for (int o = 16; o > 0; o >>= 1) p1 += __shfl_down_sync(0xffffffffu, p1, o);
    if (lane == 0) g_p1[w] = p1;
}

// ---- final: edge embeddings + logits, CSR-ordered, shuffle-free edge loop ----
__global__ void k_edge_out(const float* __restrict__ Wf,
                           const float* __restrict__ bf,
                           float* __restrict__ logits,
                           float* __restrict__ emb) {
    int gid = blockIdx.x * blockDim.x + threadIdx.x;
    int w = gid >> 5, lane = gid & 31;
    if (w >= N_NODES) return;
    const float4* node4 = (const float4*)g_node;
    float4 w1 = __ldg((const float4*)Wf + 32 + lane);
    float bias0 = __ldg(bf);

    float4 dv = node4[(size_t)w * 32 + lane];
    float p2 = dv.x*w1.x + dv.y*w1.y + dv.z*w1.z + dv.w*w1.w;
    #pragma unroll
    for (int o = 16; o > 0; o >>= 1) p2 += __shfl_down_sync(0xffffffffu, p2, o);
    float p2b = p2 + bias0;   // valid on lane 0 (only lane 0 uses it)

    int b = g_off_d[w];
    int e = min(b + g_len_d[w], N_EDGES);
    int i = b;
    for (; i + 2 <= e; i += 2) {
        int eid0 = min(max(g_lst_d[i],     0), N_EDGES - 1);
        int eid1 = min(max(g_lst_d[i + 1], 0), N_EDGES - 1);
        int s0   = min(max(g_src_d[i],     0), N_NODES - 1);
        int s1   = min(max(g_src_d[i + 1], 0), N_NODES - 1);
        float4 sv0 = node4[(size_t)s0 * 32 + lane];
        float4 sv1 = node4[(size_t)s1 * 32 + lane];
        __stcs((float4*)emb + (size_t)eid0 * 64 + lane, sv0);
        __stcs((float4*)emb + (size_t)eid0 * 64 + 32 + lane, dv);
        __stcs((float4*)emb + (size_t)eid1 * 64 + lane, sv1);
        __stcs((float4*)emb + (size_t)eid1 * 64 + 32 + lane, dv);
        if (lane == 0) {
            __stcs(logits + eid0, g_p1[s0] + p2b);
            __stcs(logits + eid1, g_p1[s1] + p2b);
        }
    }
    for (; i < e; i++) {
        int eid = min(max(g_lst_d[i], 0), N_EDGES - 1);
        int s   = min(max(g_src_d[i], 0), N_NODES - 1);
        float4 sv = node4[(size_t)s * 32 + lane];
        __stcs((float4*)emb + (size_t)eid * 64 + lane, sv);
        __stcs((float4*)emb + (size_t)eid * 64 + 32 + lane, dv);
        if (lane == 0) __stcs(logits + eid, g_p1[s] + p2b);
    }
}

extern "C" void kernel_launch(void* const* d_in, const int* in_sizes, int n_in,
                              void* d_out, int out_size) {
    const float* edge_attr = (const float*)d_in[0];
    const void*  eidx      = d_in[1];
    const float* W0e = (const float*)d_in[2];
    const float* b0e = (const float*)d_in[3];
    const float* W0n = (const float*)d_in[4];
    const float* b0n = (const float*)d_in[5];
    const float* W1e = (const float*)d_in[6];
    const float* b1e = (const float*)d_in[7];
    const float* W1n = (const float*)d_in[8];
    const float* b1n = (const float*)d_in[9];
    const float* Wf  = (const float*)d_in[10];
    const float* bf  = (const float*)d_in[11];

    float* out_logits = (float*)d_out;
    float* out_emb    = out_logits + N_EDGES;
    float* out_node   = out_emb + (size_t)N_EDGES * 2 * FD;

    cudaFuncSetAttribute(k_gemm_mma, cudaFuncAttributeMaxDynamicSharedMemorySize, SMTOT);

    const int TB = 256;
    int gn   = (N_NODES + TB - 1) / TB;
    int ge2  = (N_EDGES / 2 + TB - 1) / TB;
    int gw   = (N_NODES * 32 + TB - 1) / TB;
    int gw2  = (N_NODES * 64 + TB - 1) / TB;
    int ggm  = (N_NODES + 127) / 128;

    k_prep<<<512, TB>>>(W0e, W0n, W1e, W1n, (const int*)eidx);
    k_hist<<<ge2, TB>>>(eidx);
    k_alloc<<<gn, TB>>>();
    k_fill<<<ge2, TB>>>(eidx);

    k_gather_means<<<gw2, TB>>>(edge_attr);

    k_gemm_mma<<<ggm, TB, SMTOT>>>(0, b0e, 0, nullptr);
    k_gather_neigh<<<gw, TB>>>();
    k_gemm_mma<<<ggm, TB, SMTOT>>>(1, b0n, 1, nullptr);

    k_gemm_mma<<<ggm, TB, SMTOT>>>(2, b1e, 0, nullptr);
    k_gather_neigh<<<gw, TB>>>();
    k_gemm_mma<<<ggm, TB, SMTOT>>>(3, b1n, 1, out_node);

    k_node_logit<<<gw, TB>>>(Wf);
    k_edge_out<<<gw, TB>>>(Wf, bf, out_logits, out_emb);
}

// round 15
// speedup vs baseline: 1.0109x; 1.0109x over previous
#include <cuda_runtime.h>
#include <cuda_bf16.h>
#include <cstdint>

#define N_NODES 50000
#define N_EDGES 800000
#define FD      128
#define NF4     (N_NODES * (FD/4))

// ---- scratch (static __device__ arrays: allocation-free, zero-initialized) ----
__device__ __align__(16) float g_node [N_NODES * FD];
__device__ __align__(16) float g_emean[N_NODES * FD];
__device__ __align__(16) float g_h    [N_NODES * FD];
__device__ __align__(16) float g_tmp  [N_NODES * FD];
__device__ __align__(16) __nv_bfloat16 g_wh[4 * 256 * 128];
__device__ __align__(16) __nv_bfloat16 g_wl[4 * 256 * 128];
__device__ int g_cnt_d[N_NODES];
__device__ int g_cnt_s[N_NODES];
__device__ int g_len_d[N_NODES];
__device__ int g_len_s[N_NODES];
__device__ int g_off_d[N_NODES];
__device__ int g_off_s[N_NODES];
__device__ int g_cur_d[N_NODES];
__device__ int g_cur_s[N_NODES];
__device__ int g_lst_d[N_EDGES];
__device__ int g_src_d[N_EDGES];
__device__ int g_lst_s[N_EDGES];
__device__ int g_tot_d;
__device__ int g_tot_s;
__device__ int g_mode;

// ======================= helpers =======================
__device__ __forceinline__ uint32_t smem_u32(const void* p) {
    uint32_t a;
    asm("{ .reg .u64 t; cvta.to.shared.u64 t, %1; cvt.u32.u64 %0, t; }"
        : "=r"(a) : "l"(p));
    return a;
}

__device__ __forceinline__ void ldm_x4(uint32_t& r0, uint32_t& r1, uint32_t& r2,
                                       uint32_t& r3, uint32_t addr) {
    asm volatile("ldmatrix.sync.aligned.m8n8.x4.shared.b16 {%0,%1,%2,%3}, [%4];"
                 : "=r"(r0), "=r"(r1), "=r"(r2), "=r"(r3) : "r"(addr));
}

__device__ __forceinline__ void mma16816(float& d0, float& d1, float& d2, float& d3,
                                         uint32_t a0, uint32_t a1, uint32_t a2, uint32_t a3,
                                         uint32_t b0, uint32_t b1) {
    asm volatile("mma.sync.aligned.m16n8k16.row.col.f32.bf16.bf16.f32 "
                 "{%0,%1,%2,%3}, {%4,%5,%6,%7}, {%8,%9}, {%0,%1,%2,%3};"
                 : "+f"(d0), "+f"(d1), "+f"(d2), "+f"(d3)
                 : "r"(a0), "r"(a1), "r"(a2), "r"(a3), "r"(b0), "r"(b1));
}

// ======================= fused W prep (4 slots) + dtype detect =======================
__global__ void k_prep(const float* __restrict__ W0e, const float* __restrict__ W0n,
                       const float* __restrict__ W1e, const float* __restrict__ W1n,
                       const int* __restrict__ idx32) {
    int slot = blockIdx.x >> 7;
    const float* W = (slot == 0) ? W0e : (slot == 1) ? W0n : (slot == 2) ? W1e : W1n;
    int idx = (blockIdx.x & 127) * 256 + threadIdx.x;
    int n = idx >> 8, k = idx & 255;
    float x = W[k * 128 + n];
    __nv_bfloat16 hi = __float2bfloat16_rn(x);
    __nv_bfloat16 lo = __float2bfloat16_rn(x - __bfloat162float(hi));
    g_wh[slot * 32768 + n * 256 + k] = hi;
    g_wl[slot * 32768 + n * 256 + k] = lo;
    if (blockIdx.x == 0 && threadIdx.x == 0) {
        int nz = 0;
        for (int j = 0; j < 512; j++) nz += (idx32[2 * j + 1] != 0);
        g_mode = (nz == 0) ? 1 : 0;
    }
}

// detector must run before k_hist too (hist reads g_mode); tiny standalone copy
__global__ void k_detect(const int* __restrict__ idx32) {
    if (blockIdx.x == 0 && threadIdx.x == 0) {
        int nz = 0;
        for (int j = 0; j < 512; j++) nz += (idx32[2 * j + 1] != 0);
        g_mode = (nz == 0) ? 1 : 0;
    }
}

__device__ __forceinline__ int clampn(int v) { return min(max(v, 0), N_NODES - 1); }

__device__ __forceinline__ void load_sd2(const void* __restrict__ idx, int e2,
                                         int& s0, int& d0, int& s1, int& d1) {
    if (g_mode) {
        const longlong2* p = (const longlong2*)idx;
        longlong2 sp = p[e2];
        longlong2 dp = p[e2 + N_EDGES / 2];
        s0 = clampn((int)sp.x); s1 = clampn((int)sp.y);
        d0 = clampn((int)dp.x); d1 = clampn((int)dp.y);
    } else {
        const int2* p = (const int2*)idx;
        int2 sp = p[e2];
        int2 dp = p[e2 + N_EDGES / 2];
        s0 = clampn(sp.x); s1 = clampn(sp.y);
        d0 = clampn(dp.x); d1 = clampn(dp.y);
    }
}

__global__ void k_hist(const void* __restrict__ idx) {
    int t = blockIdx.x * blockDim.x + threadIdx.x;
    if (t >= N_EDGES / 2) return;
    int s0, d0, s1, d1;
    load_sd2(idx, t, s0, d0, s1, d1);
    atomicAdd(&g_cnt_d[d0], 1);
    atomicAdd(&g_cnt_d[d1], 1);
    atomicAdd(&g_cnt_s[s0], 1);
    atomicAdd(&g_cnt_s[s1], 1);
}

__global__ void k_alloc() {
    int i = blockIdx.x * blockDim.x + threadIdx.x;
    if (i >= N_NODES) return;
    int cd = g_cnt_d[i];
    g_cnt_d[i] = 0;
    g_len_d[i] = cd;
    int od = atomicAdd(&g_tot_d, cd);
    g_off_d[i] = od;
    g_cur_d[i] = od;
    int cs = g_cnt_s[i];
    g_cnt_s[i] = 0;
    g_len_s[i] = cs;
    int os = atomicAdd(&g_tot_s, cs);
    g_off_s[i] = os;
    g_cur_s[i] = os;
}

__global__ void k_fill(const void* __restrict__ idx) {
    int t = blockIdx.x * blockDim.x + threadIdx.x;
    if (t == 0) { g_tot_d = 0; g_tot_s = 0; }
    if (t >= N_EDGES / 2) return;
    int s0, d0, s1, d1;
    load_sd2(idx, t, s0, d0, s1, d1);
    int e0 = 2 * t, e1 = 2 * t + 1;
    int pd0 = min(max(atomicAdd(&g_cur_d[d0], 1), 0), N_EDGES - 1);
    g_lst_d[pd0] = e0; g_src_d[pd0] = s0;
    int pd1 = min(max(atomicAdd(&g_cur_d[d1], 1), 0), N_EDGES - 1);
    g_lst_d[pd1] = e1; g_src_d[pd1] = s1;
    int ps0 = min(max(atomicAdd(&g_cur_s[s0], 1), 0), N_EDGES - 1);
    g_lst_s[ps0] = e0;
    int ps1 = min(max(atomicAdd(&g_cur_s[s1], 1), 0), N_EDGES - 1);
    g_lst_s[ps1] = e1;
}

// ---- 4-deep unrolled mean gather over a CSR segment (warp per node) ----
__device__ __forceinline__ float4 seg_mean_rows(const float4* __restrict__ base,
                                                const int* __restrict__ lst,
                                                int b, int n, int lane, int clampmax) {
    int e = min(b + n, N_EDGES);
    float4 acc = make_float4(0.f, 0.f, 0.f, 0.f);
    int i = b;
    for (; i + 4 <= e; i += 4) {
        int i0 = min(max(lst[i],     0), clampmax);
        int i1 = min(max(lst[i + 1], 0), clampmax);
        int i2 = min(max(lst[i + 2], 0), clampmax);
        int i3 = min(max(lst[i + 3], 0), clampmax);
        float4 v0 = base[(size_t)i0 * 32 + lane];
        float4 v1 = base[(size_t)i1 * 32 + lane];
        float4 v2 = base[(size_t)i2 * 32 + lane];
        float4 v3 = base[(size_t)i3 * 32 + lane];
        acc.x += (v0.x + v1.x) + (v2.x + v3.x);
        acc.y += (v0.y + v1.y) + (v2.y + v3.y);
        acc.z += (v0.z + v1.z) + (v2.z + v3.z);
        acc.w += (v0.w + v1.w) + (v2.w + v3.w);
    }
    for (; i < e; i++) {
        int i0 = min(max(lst[i], 0), clampmax);
        float4 v = base[(size_t)i0 * 32 + lane];
        acc.x += v.x; acc.y += v.y; acc.z += v.z; acc.w += v.w;
    }
    float inv = 1.0f / fmaxf((float)n, 1.0f);
    acc.x *= inv; acc.y *= inv; acc.z *= inv; acc.w *= inv;
    return acc;
}

// two warps per node: even warp does dst-mean -> g_node, odd warp src-mean -> g_emean
__global__ void k_gather_means(const float* __restrict__ ea) {
    int gid = blockIdx.x * blockDim.x + threadIdx.x;
    int wg = gid >> 5, lane = gid & 31;
    int w = wg >> 1;
    if (w >= N_NODES) return;
    const float4* ea4 = (const float4*)ea;
    if ((wg & 1) == 0) {
        ((float4*)g_node)[(size_t)w * 32 + lane] =
            seg_mean_rows(ea4, g_lst_d, g_off_d[w], g_len_d[w], lane, N_EDGES - 1);
    } else {
        ((float4*)g_emean)[(size_t)w * 32 + lane] =
            seg_mean_rows(ea4, g_lst_s, g_off_s[w], g_len_s[w], lane, N_EDGES - 1);
    }
}

__global__ void k_gather_neigh() {
    int gid = blockIdx.x * blockDim.x + threadIdx.x;
    int w = gid >> 5, lane = gid & 31;
    if (w >= N_NODES) return;
    ((float4*)g_tmp)[(size_t)w * 32 + lane] =
        seg_mean_rows((const float4*)g_h, g_src_d, g_off_d[w], g_len_d[w], lane,
                      N_NODES - 1);
}

// ======================= bf16 split-precision HMMA GEMM (double-buffered) =======================
#define SROW   40
#define BUFB   10240
#define BUFSTR (4 * BUFB)
#define SMTOT  (2 * BUFSTR)

__global__ void __launch_bounds__(256, 2) k_gemm_mma(
        int slot, const float* __restrict__ bias, int sel, float* __restrict__ out2) {
    extern __shared__ __align__(16) char dsm[];
    const float* A;
    const float* Bm;
    float* out;
    if (sel == 0) { A = g_node; Bm = g_emean; out = g_h; }
    else          { A = g_h;    Bm = g_tmp;   out = g_node; }
    const __nv_bfloat16* Wh = g_wh + (size_t)slot * 32768;
    const __nv_bfloat16* Wl = g_wl + (size_t)slot * 32768;

    int tid  = threadIdx.x;
    int lane = tid & 31;
    int wid  = tid >> 5;
    int m0   = blockIdx.x * 128;
    int warp_m = wid >> 2;
    int warp_n = wid & 3;

    int l7 = lane & 7;
    int a_ro = l7 + ((lane >> 3) & 1) * 8;
    int a_ko = (lane >> 4) * 8;
    int b_no = l7 + (lane >> 4) * 8;
    int b_ko = ((lane >> 3) & 1) * 8;

    float acc[4][4][4];
    #pragma unroll
    for (int i = 0; i < 4; i++)
        #pragma unroll
        for (int j = 0; j < 4; j++)
            #pragma unroll
            for (int r = 0; r < 4; r++) acc[i][j][r] = 0.f;

    {
        __nv_bfloat16* Ah = (__nv_bfloat16*)(dsm);
        __nv_bfloat16* Al = (__nv_bfloat16*)(dsm + BUFB);
        __nv_bfloat16* Bh = (__nv_bfloat16*)(dsm + 2 * BUFB);
        __nv_bfloat16* Bl = (__nv_bfloat16*)(dsm + 3 * BUFB);
        #pragma unroll
        for (int it = 0; it < 4; it++) {
            int f = tid + it * 256;
            int row = f >> 3, q = f & 7;
            int grow = m0 + row;
            float4 v = make_float4(0.f, 0.f, 0.f, 0.f);
            if (grow < N_NODES) v = *(const float4*)(A + (size_t)grow * FD + q * 4);
            __nv_bfloat162 h0 = __float22bfloat162_rn(make_float2(v.x, v.y));
            __nv_bfloat162 h1 = __float22bfloat162_rn(make_float2(v.z, v.w));
            float2 f0 = __bfloat1622float2(h0);
            float2 f1 = __bfloat1622float2(h1);
            __nv_bfloat162 l0 = __float22bfloat162_rn(make_float2(v.x - f0.x, v.y - f0.y));
            __nv_bfloat162 l1 = __float22bfloat162_rn(make_float2(v.z - f1.x, v.w - f1.y));
            uint2 uh, ul;
            uh.x = *(uint32_t*)&h0; uh.y = *(uint32_t*)&h1;
            ul.x = *(uint32_t*)&l0; ul.y = *(uint32_t*)&l1;
            *(uint2*)&Ah[row * SROW + q * 4] = uh;
            *(uint2*)&Al[row * SROW + q * 4] = ul;
            *(uint2*)&Bh[row * SROW + q * 4] = *(const uint2*)(Wh + row * 256 + q * 4);
            *(uint2*)&Bl[row * SROW + q * 4] = *(const uint2*)(Wl + row * 256 + q * 4);
        }
    }
    __syncthreads();

    #pragma unroll 1
    for (int ch = 0; ch < 8; ch++) {
        char* cur = dsm + (ch & 1) * BUFSTR;
        char* nxt = dsm + ((ch + 1) & 1) * BUFSTR;
        __nv_bfloat16* Ah = (__nv_bfloat16*)(cur);
        __nv_bfloat16* Al = (__nv_bfloat16*)(cur + BUFB);
        __nv_bfloat16* Bh = (__nv_bfloat16*)(cur + 2 * BUFB);
        __nv_bfloat16* Bl = (__nv_bfloat16*)(cur + 3 * BUFB);

        float4 av[4];
        if (ch < 7) {
            int kb2 = (ch + 1) * 32;
            const float* X2 = (kb2 < 128) ? A : Bm;
            int ko2 = kb2 & 127;
            #pragma unroll
            for (int it = 0; it < 4; it++) {
                int f = tid + it * 256;
                int row = f >> 3, q = f & 7;
                int grow = m0 + row;
                av[it] = make_float4(0.f, 0.f, 0.f, 0.f);
                if (grow < N_NODES)
                    av[it] = *(const float4*)(X2 + (size_t)grow * FD + ko2 + q * 4);
            }
            __nv_bfloat16* nBh = (__nv_bfloat16*)(nxt + 2 * BUFB);
            __nv_bfloat16* nBl = (__nv_bfloat16*)(nxt + 3 * BUFB);
            #pragma unroll
            for (int it = 0; it < 4; it++) {
                int f = tid + it * 256;
                int n = f >> 3, q = f & 7;
                *(uint2*)&nBh[n * SROW + q * 4] = *(const uint2*)(Wh + n * 256 + kb2 + q * 4);
                *(uint2*)&nBl[n * SROW + q * 4] = *(const uint2*)(Wl + n * 256 + kb2 + q * 4);
            }
        }

        #pragma unroll
        for (int ks = 0; ks < 2; ks++) {
            int kl = ks * 16;
            uint32_t bh[2][4], bl[2][4];
            #pragma unroll
            for (int jp = 0; jp < 2; jp++) {
                int nn = warp_n * 32 + jp * 16 + b_no;
                int kk = kl + b_ko;
                ldm_x4(bh[jp][0], bh[jp][1], bh[jp][2], bh[jp][3],
                       smem_u32(&Bh[nn * SROW + kk]));
                ldm_x4(bl[jp][0], bl[jp][1], bl[jp][2], bl[jp][3],
                       smem_u32(&Bl[nn * SROW + kk]));
            }
            #pragma unroll
            for (int i = 0; i < 4; i++) {
                int row = warp_m * 64 + i * 16 + a_ro;
                int kk  = kl + a_ko;
                uint32_t ah0, ah1, ah2, ah3, al0, al1, al2, al3;
                ldm_x4(ah0, ah1, ah2, ah3, smem_u32(&Ah[row * SROW + kk]));
                ldm_x4(al0, al1, al2, al3, smem_u32(&Al[row * SROW + kk]));
                #pragma unroll
                for (int j = 0; j < 4; j++) {
                    uint32_t b0h = bh[j >> 1][(j & 1) * 2], b1h = bh[j >> 1][(j & 1) * 2 + 1];
                    uint32_t b0l = bl[j >> 1][(j & 1) * 2], b1l = bl[j >> 1][(j & 1) * 2 + 1];
                    float* c = acc[i][j];
                    mma16816(c[0], c[1], c[2], c[3], ah0, ah1, ah2, ah3, b0h, b1h);
                    mma16816(c[0], c[1], c[2], c[3], ah0, ah1, ah2, ah3, b0l, b1l);
                    mma16816(c[0], c[1], c[2], c[3], al0, al1, al2, al3, b0h, b1h);
                }
            }
        }

        if (ch < 7) {
            __nv_bfloat16* nAh = (__nv_bfloat16*)(nxt);
            __nv_bfloat16* nAl = (__nv_bfloat16*)(nxt + BUFB);
            #pragma unroll
            for (int it = 0; it < 4; it++) {
                int f = tid + it * 256;
                int row = f >> 3, q = f & 7;
                float4 v = av[it];
                __nv_bfloat162 h0 = __float22bfloat162_rn(make_float2(v.x, v.y));
                __nv_bfloat162 h1 = __float22bfloat162_rn(make_float2(v.z, v.w));
                float2 f0 = __bfloat1622float2(h0);
                float2 f1 = __bfloat1622float2(h1);
                __nv_bfloat162 l0 = __float22bfloat162_rn(make_float2(v.x - f0.x, v.y - f0.y));
                __nv_bfloat162 l1 = __float22bfloat162_rn(make_float2(v.z - f1.x, v.w - f1.y));
                uint2 uh, ul;
                uh.x = *(uint32_t*)&h0; uh.y = *(uint32_t*)&h1;
                ul.x = *(uint32_t*)&l0; ul.y = *(uint32_t*)&l1;
                *(uint2*)&nAh[row * SROW + q * 4] = uh;
                *(uint2*)&nAl[row * SROW + q * 4] = ul;
            }
        }
        __syncthreads();
    }

    int gID = lane >> 2, tig = lane & 3;
    #pragma unroll
    for (int j = 0; j < 4; j++) {
        int col = warp_n * 32 + j * 8 + tig * 2;
        float bv0 = __ldg(bias + col);
        float bv1 = __ldg(bias + col + 1);
        #pragma unroll
        for (int i = 0; i < 4; i++) {
            int r0 = m0 + warp_m * 64 + i * 16 + gID;
            float* c = acc[i][j];
            if (r0 < N_NODES) {
                float2 o;
                o.x = fmaxf(c[0] + bv0, 0.f);
                o.y = fmaxf(c[1] + bv1, 0.f);
                *(float2*)(out + (size_t)r0 * FD + col) = o;
                if (out2) __stcs((float2*)(out2 + (size_t)r0 * FD + col), o);
            }
            int r1 = r0 + 8;
            if (r1 < N_NODES) {
                float2 o;
                o.x = fmaxf(c[2] + bv0, 0.f);
                o.y = fmaxf(c[3] + bv1, 0.f);
                *(float2*)(out + (size_t)r1 * FD + col) = o;
                if (out2) __stcs((float2*)(out2 + (size_t)r1 * FD + col), o);
            }
        }
    }
}

// ---- final: edge embeddings + logits, CSR-ordered (warp per dst node, 2-deep) ----
__global__ void k_edge_out(const float* __restrict__ Wf,
                           const float* __restrict__ bf,
                           float* __restrict__ logits,
                           float* __restrict__ emb) {
    int gid = blockIdx.x * blockDim.x + threadIdx.x;
    int w = gid >> 5, lane = gid & 31;
    if (w >= N_NODES) return;
    const float4* node4 = (const float4*)g_node;
    const float4* wf4 = (const float4*)Wf;
    float4 w0 = __ldg(wf4 + lane);
    float4 w1 = __ldg(wf4 + 32 + lane);
    float bias0 = __ldg(bf);

    float4 dv = node4[(size_t)w * 32 + lane];
    float p2 = dv.x*w1.x + dv.y*w1.y + dv.z*w1.z + dv.w*w1.w;
    #pragma unroll
    for (int o = 16; o > 0; o >>= 1) p2 += __shfl_down_sync(0xffffffffu, p2, o);
    p2 = __shfl_sync(0xffffffffu, p2, 0);

    int b = g_off_d[w];
    int e = min(b + g_len_d[w], N_EDGES);
    int i = b;
    for (; i + 2 <= e; i += 2) {
        int eid0 = min(max(g_lst_d[i],     0), N_EDGES - 1);
        int eid1 = min(max(g_lst_d[i + 1], 0), N_EDGES - 1);
        int s0   = min(max(g_src_d[i],     0), N_NODES - 1);
        int s1   = min(max(g_src_d[i + 1], 0), N_NODES - 1);
        float4 sv0 = node4[(size_t)s0 * 32 + lane];
        float4 sv1 = node4[(size_t)s1 * 32 + lane];
        __stcs((float4*)emb + (size_t)eid0 * 64 + lane, sv0);
        __stcs((float4*)emb + (size_t)eid0 * 64 + 32 + lane, dv);
        __stcs((float4*)emb + (size_t)eid1 * 64 + lane, sv1);
        __stcs((float4*)emb + (size_t)eid1 * 64 + 32 + lane, dv);
        float p1a = sv0.x*w0.x + sv0.y*w0.y + sv0.z*w0.z + sv0.w*w0.w;
        float p1b = sv1.x*w0.x + sv1.y*w0.y + sv1.z*w0.z + sv1.w*w0.w;
        #pragma unroll
        for (int o = 16; o > 0; o >>= 1) {
            p1a += __shfl_down_sync(0xffffffffu, p1a, o);
            p1b += __shfl_down_sync(0xffffffffu, p1b, o);
        }
        if (lane == 0) {
            __stcs(logits + eid0, p1a + p2 + bias0);
            __stcs(logits + eid1, p1b + p2 + bias0);
        }
    }
    for (; i < e; i++) {
        int eid = min(max(g_lst_d[i], 0), N_EDGES - 1);
        int s   = min(max(g_src_d[i], 0), N_NODES - 1);
        float4 sv = node4[(size_t)s * 32 + lane];
        __stcs((float4*)emb + (size_t)eid * 64 + lane, sv);
        __stcs((float4*)emb + (size_t)eid * 64 + 32 + lane, dv);
        float p1 = sv.x*w0.x + sv.y*w0.y + sv.z*w0.z + sv.w*w0.w;
        #pragma unroll
        for (int o = 16; o > 0; o >>= 1) p1 += __shfl_down_sync(0xffffffffu, p1, o);
        if (lane == 0) __stcs(logits + eid, p1 + p2 + bias0);
    }
}

extern "C" void kernel_launch(void* const* d_in, const int* in_sizes, int n_in,
                              void* d_out, int out_size) {
    const float* edge_attr = (const float*)d_in[0];
    const void*  eidx      = d_in[1];
    const float* W0e = (const float*)d_in[2];
    const float* b0e = (const float*)d_in[3];
    const float* W0n = (const float*)d_in[4];
    const float* b0n = (const float*)d_in[5];
    const float* W1e = (const float*)d_in[6];
    const float* b1e = (const float*)d_in[7];
    const float* W1n = (const float*)d_in[8];
    const float* b1n = (const float*)d_in[9];
    const float* Wf  = (const float*)d_in[10];
    const float* bf  = (const float*)d_in[11];

    float* out_logits = (float*)d_out;
    float* out_emb    = out_logits + N_EDGES;
    float* out_node   = out_emb + (size_t)N_EDGES * 2 * FD;

    cudaFuncSetAttribute(k_gemm_mma, cudaFuncAttributeMaxDynamicSharedMemorySize, SMTOT);

    // one-time host-side resources (no device memory; deterministic work per call)
    static cudaStream_t s2 = nullptr;
    static cudaEvent_t evFork = nullptr, evJoin = nullptr;
    if (!s2) {
        cudaStreamCreateWithFlags(&s2, cudaStreamNonBlocking);
        cudaEventCreateWithFlags(&evFork, cudaEventDisableTiming);
        cudaEventCreateWithFlags(&evJoin, cudaEventDisableTiming);
    }

    const int TB = 256;
    int gn   = (N_NODES + TB - 1) / TB;
    int ge2  = (N_EDGES / 2 + TB - 1) / TB;
    int gw   = (N_NODES * 32 + TB - 1) / TB;
    int gw2  = (N_NODES * 64 + TB - 1) / TB;
    int ggm  = (N_NODES + 127) / 128;

    // dtype detect on the main stream (needed by CSR chain)
    k_detect<<<1, 32>>>((const int*)eidx);

    // fork: W prep runs on s2, concurrent with CSR build + gather_means
    cudaEventRecord(evFork, 0);
    cudaStreamWaitEvent(s2, evFork, 0);
    k_prep<<<512, TB, 0, s2>>>(W0e, W0n, W1e, W1n, (const int*)eidx);
    cudaEventRecord(evJoin, s2);

    // CSR build (main stream)
    k_hist<<<ge2, TB>>>(eidx);
    k_alloc<<<gn, TB>>>();
    k_fill<<<ge2, TB>>>(eidx);

    // initial means (node_attr by dst, emean by src)
    k_gather_means<<<gw2, TB>>>(edge_attr);

    // join: GEMMs need g_wh/g_wl
    cudaStreamWaitEvent(0, evJoin, 0);

    // layer 0
    k_gemm_mma<<<ggm, TB, SMTOT>>>(0, b0e, 0, nullptr);
    k_gather_neigh<<<gw, TB>>>();
    k_gemm_mma<<<ggm, TB, SMTOT>>>(1, b0n, 1, nullptr);

    // layer 1
    k_gemm_mma<<<ggm, TB, SMTOT>>>(2, b1e, 0, nullptr);
    k_gather_neigh<<<gw, TB>>>();
    k_gemm_mma<<<ggm, TB, SMTOT>>>(3, b1n, 1, out_node);

    // outputs
    k_edge_out<<<gw, TB>>>(Wf, bf, out_logits, out_emb);
}